// round 16
// baseline (speedup 1.0000x reference)
#include <cuda_runtime.h>
#include <cstdint>

#define PP 6
#define NF 10
#define SEG 1944              // float4 per hi-segment (6^5 / 4)
#define SEGB 31104            // bytes per segment stage
#define GRID 288              // 288 * 27 = 7776 segments: perfectly even split
#define SEGS_PER_BLK 27
#define TPB 256
#define NSTAGE 3
#define PF_AHEAD 12           // prefetch distance in stages (~107MB chip-wide window)

__device__ float g_partials[GRID];
__device__ unsigned int g_count;   // zero-init; last block resets each run

__device__ __forceinline__ uint32_t smem_u32(const void* p) {
    uint32_t a;
    asm("{ .reg .u64 t; cvta.to.shared.u64 t, %1; cvt.u32.u64 %0, t; }"
        : "=r"(a) : "l"(p));
    return a;
}
__device__ __forceinline__ void mbar_init(uint32_t mbar, uint32_t count) {
    asm volatile("mbarrier.init.shared.b64 [%0], %1;" :: "r"(mbar), "r"(count) : "memory");
}
__device__ __forceinline__ void mbar_expect_tx(uint32_t mbar, uint32_t bytes) {
    asm volatile("mbarrier.arrive.expect_tx.shared.b64 _, [%0], %1;"
                 :: "r"(mbar), "r"(bytes) : "memory");
}
__device__ __forceinline__ void mbar_arrive(uint32_t mbar) {
    asm volatile("mbarrier.arrive.release.cta.shared::cta.b64 _, [%0];"
                 :: "r"(mbar) : "memory");
}
// Bulk copy with L2 evict-first policy (y is read-once streaming data).
__device__ __forceinline__ void bulk_ld_stream(uint32_t dst_smem, const void* src,
                                               uint32_t bytes, uint32_t mbar,
                                               uint64_t policy) {
    asm volatile(
        "cp.async.bulk.shared::cluster.global.mbarrier::complete_tx::bytes.L2::cache_hint"
        " [%0], [%1], %2, [%3], %4;"
        :: "r"(dst_smem), "l"(src), "r"(bytes), "r"(mbar), "l"(policy) : "memory");
}
// L2-only prefetch: deepens the DRAM-side request window beyond what the smem
// ring can hold; subsequent TMA fills then hit L2 instead of DRAM.
__device__ __forceinline__ void bulk_prefetch_l2(const void* src, uint32_t bytes,
                                                 uint64_t policy) {
    asm volatile(
        "cp.async.bulk.prefetch.L2.global.L2::cache_hint [%0], %1, %2;"
        :: "l"(src), "r"(bytes), "l"(policy) : "memory");
}
__device__ __forceinline__ uint64_t make_evict_first_policy() {
    uint64_t pol;
    asm("createpolicy.fractional.L2::evict_first.b64 %0, 1.0;" : "=l"(pol));
    return pol;
}
__device__ __forceinline__ void mbar_wait(uint32_t mbar, uint32_t parity) {
    uint32_t done;
    asm volatile(
        "{ .reg .pred p; mbarrier.try_wait.parity.acquire.cta.shared::cta.b64 p, [%1], %2;"
        " selp.b32 %0, 1, 0, p; }"
        : "=r"(done) : "r"(mbar), "r"(parity) : "memory");
    if (!done) {
        asm volatile(
            "{ .reg .pred P1; W%=:"
            " mbarrier.try_wait.parity.acquire.cta.shared::cta.b64 P1, [%0], %1, 0x989680;"
            " @P1 bra.uni D%=; bra.uni W%=; D%=: }"
            :: "r"(mbar), "r"(parity) : "memory");
    }
}

__global__ void __launch_bounds__(TPB, 2) sum_kernel(const float* __restrict__ X,
                                                     const float* __restrict__ a,
                                                     const float* __restrict__ b,
                                                     const float4* __restrict__ y4,
                                                     float* __restrict__ out) {
    extern __shared__ __align__(16) float4 ring[];   // NSTAGE * SEG float4
    __shared__ float h[NF][PP];
    __shared__ unsigned long long mbar_store[2 * NSTAGE];  // [full0,empty0,full1,...]
    __shared__ float warp_sums[TPB / 32];

    const int tid = threadIdx.x;
    const int blk = blockIdx.x;
    const uint32_t mb0 = smem_u32(mbar_store);
    // full[s] = mb0 + 16s, empty[s] = mb0 + 16s + 8
    const int base = blk * SEGS_PER_BLK;
    const char* ybase = (const char*)y4;

    const uint64_t pol = make_evict_first_policy();

    if (tid == 0) {
        #pragma unroll
        for (int s = 0; s < NSTAGE; s++) {
            mbar_init(mb0 + 16u * s, 1);             // full: tx-based
            mbar_init(mb0 + 16u * s + 8u, TPB / 32); // empty: one arrive per warp
        }
        // Kick off the first NSTAGE stage fills; they overlap h/creg setup.
        #pragma unroll
        for (int k = 0; k < NSTAGE; k++) {
            mbar_expect_tx(mb0 + 16u * k, SEGB);
            bulk_ld_stream(smem_u32(&ring[k * SEG]),
                           ybase + (size_t)(base + k) * SEGB, SEGB,
                           mb0 + 16u * k, pol);
        }
        // Prime the L2 prefetch window for stages NSTAGE..PF_AHEAD-1.
        #pragma unroll
        for (int k = NSTAGE; k < PF_AHEAD; k++)
            if (k < SEGS_PER_BLK)
                bulk_prefetch_l2(ybase + (size_t)(base + k) * SEGB, SEGB, pol);
    }

    // Membership values h[i][j]
    if (tid < NF * PP) {
        int i = tid / PP;
        float d  = a[tid] - X[i];
        float bb = b[tid];
        h[i][tid % PP] = expf(-(d * d) / (2.0f * bb * bb));
    }
    __syncthreads();   // h visible + mbar init visible to all

    // Per-thread C float4s in REGISTERS: lo positions tid + 256*j are identical
    // in every segment. j=0..6 always valid, j=7 only for tid < 152.
    const bool has8 = (tid < SEG - 7 * TPB);   // tid < 152
    float4 creg[8];
    #pragma unroll
    for (int j = 0; j < 8; j++) {
        if (j < 7 || has8) {
            int f0 = 4 * (tid + 256 * j);
            float c[4];
            #pragma unroll
            for (int cc = 0; cc < 4; cc++) {
                int f = f0 + cc;
                int d4 = f % 6;  f /= 6;
                int d3 = f % 6;  f /= 6;
                int d2 = f % 6;  f /= 6;
                int d1 = f % 6;  f /= 6;
                int d0 = f;
                c[cc] = h[5][d0] * h[6][d1] * h[7][d2] * h[8][d3] * h[9][d4];
            }
            creg[j] = make_float4(c[0], c[1], c[2], c[3]);
        } else {
            creg[j] = make_float4(0.f, 0.f, 0.f, 0.f);
        }
    }

    const int lid = tid & 31;
    float acc = 0.0f;

    for (int k = 0; k < SEGS_PER_BLK; k++) {
        int slot = k % NSTAGE;
        uint32_t parity = (uint32_t)((k / NSTAGE) & 1);
        uint32_t fullb  = mb0 + 16u * slot;
        uint32_t emptyb = fullb + 8u;

        mbar_wait(fullb, parity);

        // Drain stage into registers, then release the slot so the TMA refill
        // overlaps with the FMA work below.
        const float4* st = &ring[slot * SEG];
        float4 yv[8];
        #pragma unroll
        for (int j = 0; j < 7; j++) yv[j] = st[tid + 256 * j];
        if (has8) yv[7] = st[tid + 256 * 7];
        __syncwarp();
        if (lid == 0) mbar_arrive(emptyb);

        // Producer: extend the prefetch window, then refill this slot once all
        // 8 warps have released it.
        if (tid == 0) {
            if (k + PF_AHEAD < SEGS_PER_BLK)
                bulk_prefetch_l2(ybase + (size_t)(base + k + PF_AHEAD) * SEGB, SEGB, pol);
            if (k + NSTAGE < SEGS_PER_BLK) {
                mbar_wait(emptyb, parity);   // round r completes with parity r&1
                mbar_expect_tx(fullb, SEGB);
                bulk_ld_stream(smem_u32(&ring[slot * SEG]),
                               ybase + (size_t)(base + k + NSTAGE) * SEGB, SEGB,
                               fullb, pol);
            }
        }

        // Per-stage scalar weight w = A[segment] from the 5 high digits.
        int s = base + k;
        int d0 = s / 1296;  int r = s - d0 * 1296;
        int d1 = r / 216;   r -= d1 * 216;
        int d2 = r / 36;    r -= d2 * 36;
        int d3 = r / 6;
        int d4 = r - d3 * 6;
        float w = h[0][d0] * h[1][d1] * h[2][d2] * h[3][d3] * h[4][d4];

        float a0 = 0.f, a1 = 0.f;
        #pragma unroll
        for (int j = 0; j < 7; j++) {
            float d = yv[j].x * creg[j].x;
            d = fmaf(yv[j].y, creg[j].y, d);
            d = fmaf(yv[j].z, creg[j].z, d);
            d = fmaf(yv[j].w, creg[j].w, d);
            if (j & 1) a1 += d; else a0 += d;
        }
        if (has8) {
            float d = yv[7].x * creg[7].x;
            d = fmaf(yv[7].y, creg[7].y, d);
            d = fmaf(yv[7].z, creg[7].z, d);
            d = fmaf(yv[7].w, creg[7].w, d);
            a1 += d;
        }
        acc = fmaf(w, a0 + a1, acc);
    }

    // Block reduction -> per-block partial
    #pragma unroll
    for (int off = 16; off; off >>= 1)
        acc += __shfl_xor_sync(0xffffffffu, acc, off);
    int wid = tid >> 5;
    if (lid == 0) warp_sums[wid] = acc;
    __syncthreads();
    if (tid == 0) {
        float v = 0.0f;
        #pragma unroll
        for (int w2 = 0; w2 < TPB / 32; w2++) v += warp_sums[w2];
        g_partials[blk] = v;
    }

    // Last-block-done: final reduction + den + output, reset counter.
    __shared__ bool is_last;
    __threadfence();
    __syncthreads();
    if (tid == 0) {
        unsigned int prev = atomicAdd(&g_count, 1u);
        is_last = (prev == GRID - 1);
    }
    __syncthreads();
    if (is_last) {
        float v = (tid < GRID) ? g_partials[tid] : 0.0f;
        if (tid + TPB < GRID) v += g_partials[tid + TPB];
        #pragma unroll
        for (int off = 16; off; off >>= 1)
            v += __shfl_xor_sync(0xffffffffu, v, off);
        if (lid == 0) warp_sums[wid] = v;

        __shared__ float rs[NF];
        if (tid < NF) {
            float s = 0.0f;
            #pragma unroll
            for (int j = 0; j < PP; j++) s += h[tid][j];
            rs[tid] = s;
        }
        __syncthreads();
        if (tid == 0) {
            float num = 0.0f;
            #pragma unroll
            for (int w2 = 0; w2 < TPB / 32; w2++) num += warp_sums[w2];
            float den = 1.0f;
            #pragma unroll
            for (int i = 0; i < NF; i++) den *= rs[i];
            out[0] = num / den;
            g_count = 0;   // deterministic graph replay
        }
    }
}

extern "C" void kernel_launch(void* const* d_in, const int* in_sizes, int n_in,
                              void* d_out, int out_size) {
    const float* X = (const float*)d_in[0];
    const float* a = (const float*)d_in[1];
    const float* b = (const float*)d_in[2];
    const float* y = (const float*)d_in[3];
    float* out = (float*)d_out;

    int smem_bytes = NSTAGE * SEGB;   // 93312 B
    cudaFuncSetAttribute(sum_kernel,
                         cudaFuncAttributeMaxDynamicSharedMemorySize, smem_bytes);
    sum_kernel<<<GRID, TPB, smem_bytes>>>(X, a, b, (const float4*)y, out);
}

// round 17
// speedup vs baseline: 1.3066x; 1.3066x over previous
#include <cuda_runtime.h>
#include <cstdint>

#define PP 6
#define NF 10
#define SEG 1944              // float4 per hi-segment (6^5 / 4)
#define SEGB 31104            // bytes per segment stage
#define GRID 288              // 288 * 27 = 7776 segments: perfectly even split
#define SEGS_PER_BLK 27
#define TPB 256
#define NSTAGE 3
#define PF_AHEAD (2 * NSTAGE) // prefetch distance in stages (~3 beyond the fill)

__device__ float g_partials[GRID];
__device__ unsigned int g_count;   // zero-init; last block resets each run

__device__ __forceinline__ uint32_t smem_u32(const void* p) {
    uint32_t a;
    asm("{ .reg .u64 t; cvta.to.shared.u64 t, %1; cvt.u32.u64 %0, t; }"
        : "=r"(a) : "l"(p));
    return a;
}
__device__ __forceinline__ void mbar_init(uint32_t mbar, uint32_t count) {
    asm volatile("mbarrier.init.shared.b64 [%0], %1;" :: "r"(mbar), "r"(count) : "memory");
}
__device__ __forceinline__ void mbar_expect_tx(uint32_t mbar, uint32_t bytes) {
    asm volatile("mbarrier.arrive.expect_tx.shared.b64 _, [%0], %1;"
                 :: "r"(mbar), "r"(bytes) : "memory");
}
__device__ __forceinline__ void mbar_arrive(uint32_t mbar) {
    asm volatile("mbarrier.arrive.release.cta.shared::cta.b64 _, [%0];"
                 :: "r"(mbar) : "memory");
}
// Bulk copy with L2 evict-first policy (y is read-once streaming data).
__device__ __forceinline__ void bulk_ld_stream(uint32_t dst_smem, const void* src,
                                               uint32_t bytes, uint32_t mbar,
                                               uint64_t policy) {
    asm volatile(
        "cp.async.bulk.shared::cluster.global.mbarrier::complete_tx::bytes.L2::cache_hint"
        " [%0], [%1], %2, [%3], %4;"
        :: "r"(dst_smem), "l"(src), "r"(bytes), "r"(mbar), "l"(policy) : "memory");
}
// L2-only prefetch: deepens the DRAM-side request window beyond what the smem
// ring can hold; subsequent TMA fills then hit L2 instead of DRAM.
__device__ __forceinline__ void bulk_prefetch_l2(const void* src, uint32_t bytes,
                                                 uint64_t policy) {
    asm volatile(
        "cp.async.bulk.prefetch.L2.global.L2::cache_hint [%0], %1, %2;"
        :: "l"(src), "r"(bytes), "l"(policy) : "memory");
}
__device__ __forceinline__ uint64_t make_evict_first_policy() {
    uint64_t pol;
    asm("createpolicy.fractional.L2::evict_first.b64 %0, 1.0;" : "=l"(pol));
    return pol;
}
__device__ __forceinline__ void mbar_wait(uint32_t mbar, uint32_t parity) {
    uint32_t done;
    asm volatile(
        "{ .reg .pred p; mbarrier.try_wait.parity.acquire.cta.shared::cta.b64 p, [%1], %2;"
        " selp.b32 %0, 1, 0, p; }"
        : "=r"(done) : "r"(mbar), "r"(parity) : "memory");
    if (!done) {
        asm volatile(
            "{ .reg .pred P1; W%=:"
            " mbarrier.try_wait.parity.acquire.cta.shared::cta.b64 P1, [%0], %1, 0x989680;"
            " @P1 bra.uni D%=; bra.uni W%=; D%=: }"
            :: "r"(mbar), "r"(parity) : "memory");
    }
}

__global__ void __launch_bounds__(TPB, 2) sum_kernel(const float* __restrict__ X,
                                                     const float* __restrict__ a,
                                                     const float* __restrict__ b,
                                                     const float4* __restrict__ y4,
                                                     float* __restrict__ out) {
    extern __shared__ __align__(16) float4 ring[];   // NSTAGE * SEG float4
    __shared__ float h[NF][PP];
    __shared__ unsigned long long mbar_store[2 * NSTAGE];  // [full0,empty0,full1,...]
    __shared__ float warp_sums[TPB / 32];

    const int tid = threadIdx.x;
    const int blk = blockIdx.x;
    const uint32_t mb0 = smem_u32(mbar_store);
    // full[s] = mb0 + 16s, empty[s] = mb0 + 16s + 8
    const int base = blk * SEGS_PER_BLK;
    const char* ybase = (const char*)y4;

    const uint64_t pol = make_evict_first_policy();

    if (tid == 0) {
        #pragma unroll
        for (int s = 0; s < NSTAGE; s++) {
            mbar_init(mb0 + 16u * s, 1);             // full: tx-based
            mbar_init(mb0 + 16u * s + 8u, TPB / 32); // empty: one arrive per warp
        }
        // Kick off the first NSTAGE stage fills; they overlap h/creg setup.
        #pragma unroll
        for (int k = 0; k < NSTAGE; k++) {
            mbar_expect_tx(mb0 + 16u * k, SEGB);
            bulk_ld_stream(smem_u32(&ring[k * SEG]),
                           ybase + (size_t)(base + k) * SEGB, SEGB,
                           mb0 + 16u * k, pol);
        }
        // Prime the L2 prefetch window for stages NSTAGE..PF_AHEAD-1.
        #pragma unroll
        for (int k = NSTAGE; k < PF_AHEAD; k++)
            if (k < SEGS_PER_BLK)
                bulk_prefetch_l2(ybase + (size_t)(base + k) * SEGB, SEGB, pol);
    }

    // Membership values h[i][j]
    if (tid < NF * PP) {
        int i = tid / PP;
        float d  = a[tid] - X[i];
        float bb = b[tid];
        h[i][tid % PP] = expf(-(d * d) / (2.0f * bb * bb));
    }
    __syncthreads();   // h visible + mbar init visible to all

    // Per-thread C float4s in REGISTERS: lo positions tid + 256*j are identical
    // in every segment. j=0..6 always valid, j=7 only for tid < 152.
    const bool has8 = (tid < SEG - 7 * TPB);   // tid < 152
    float4 creg[8];
    #pragma unroll
    for (int j = 0; j < 8; j++) {
        if (j < 7 || has8) {
            int f0 = 4 * (tid + 256 * j);
            float c[4];
            #pragma unroll
            for (int cc = 0; cc < 4; cc++) {
                int f = f0 + cc;
                int d4 = f % 6;  f /= 6;
                int d3 = f % 6;  f /= 6;
                int d2 = f % 6;  f /= 6;
                int d1 = f % 6;  f /= 6;
                int d0 = f;
                c[cc] = h[5][d0] * h[6][d1] * h[7][d2] * h[8][d3] * h[9][d4];
            }
            creg[j] = make_float4(c[0], c[1], c[2], c[3]);
        } else {
            creg[j] = make_float4(0.f, 0.f, 0.f, 0.f);
        }
    }

    const int lid = tid & 31;
    float acc = 0.0f;

    for (int k = 0; k < SEGS_PER_BLK; k++) {
        int slot = k % NSTAGE;
        uint32_t parity = (uint32_t)((k / NSTAGE) & 1);
        uint32_t fullb  = mb0 + 16u * slot;
        uint32_t emptyb = fullb + 8u;

        mbar_wait(fullb, parity);

        // Drain stage into registers, then release the slot so the TMA refill
        // overlaps with the FMA work below.
        const float4* st = &ring[slot * SEG];
        float4 yv[8];
        #pragma unroll
        for (int j = 0; j < 7; j++) yv[j] = st[tid + 256 * j];
        if (has8) yv[7] = st[tid + 256 * 7];
        __syncwarp();
        if (lid == 0) mbar_arrive(emptyb);

        // Producer: extend the prefetch window, then refill this slot once all
        // 8 warps have released it.
        if (tid == 0) {
            if (k + PF_AHEAD < SEGS_PER_BLK)
                bulk_prefetch_l2(ybase + (size_t)(base + k + PF_AHEAD) * SEGB, SEGB, pol);
            if (k + NSTAGE < SEGS_PER_BLK) {
                mbar_wait(emptyb, parity);   // round r completes with parity r&1
                mbar_expect_tx(fullb, SEGB);
                bulk_ld_stream(smem_u32(&ring[slot * SEG]),
                               ybase + (size_t)(base + k + NSTAGE) * SEGB, SEGB,
                               fullb, pol);
            }
        }

        // Per-stage scalar weight w = A[segment] from the 5 high digits.
        int s = base + k;
        int d0 = s / 1296;  int r = s - d0 * 1296;
        int d1 = r / 216;   r -= d1 * 216;
        int d2 = r / 36;    r -= d2 * 36;
        int d3 = r / 6;
        int d4 = r - d3 * 6;
        float w = h[0][d0] * h[1][d1] * h[2][d2] * h[3][d3] * h[4][d4];

        float a0 = 0.f, a1 = 0.f;
        #pragma unroll
        for (int j = 0; j < 7; j++) {
            float d = yv[j].x * creg[j].x;
            d = fmaf(yv[j].y, creg[j].y, d);
            d = fmaf(yv[j].z, creg[j].z, d);
            d = fmaf(yv[j].w, creg[j].w, d);
            if (j & 1) a1 += d; else a0 += d;
        }
        if (has8) {
            float d = yv[7].x * creg[7].x;
            d = fmaf(yv[7].y, creg[7].y, d);
            d = fmaf(yv[7].z, creg[7].z, d);
            d = fmaf(yv[7].w, creg[7].w, d);
            a1 += d;
        }
        acc = fmaf(w, a0 + a1, acc);
    }

    // Block reduction -> per-block partial
    #pragma unroll
    for (int off = 16; off; off >>= 1)
        acc += __shfl_xor_sync(0xffffffffu, acc, off);
    int wid = tid >> 5;
    if (lid == 0) warp_sums[wid] = acc;
    __syncthreads();
    if (tid == 0) {
        float v = 0.0f;
        #pragma unroll
        for (int w2 = 0; w2 < TPB / 32; w2++) v += warp_sums[w2];
        g_partials[blk] = v;
    }

    // Last-block-done: final reduction + den + output, reset counter.
    __shared__ bool is_last;
    __threadfence();
    __syncthreads();
    if (tid == 0) {
        unsigned int prev = atomicAdd(&g_count, 1u);
        is_last = (prev == GRID - 1);
    }
    __syncthreads();
    if (is_last) {
        float v = (tid < GRID) ? g_partials[tid] : 0.0f;
        if (tid + TPB < GRID) v += g_partials[tid + TPB];
        #pragma unroll
        for (int off = 16; off; off >>= 1)
            v += __shfl_xor_sync(0xffffffffu, v, off);
        if (lid == 0) warp_sums[wid] = v;

        __shared__ float rs[NF];
        if (tid < NF) {
            float s = 0.0f;
            #pragma unroll
            for (int j = 0; j < PP; j++) s += h[tid][j];
            rs[tid] = s;
        }
        __syncthreads();
        if (tid == 0) {
            float num = 0.0f;
            #pragma unroll
            for (int w2 = 0; w2 < TPB / 32; w2++) num += warp_sums[w2];
            float den = 1.0f;
            #pragma unroll
            for (int i = 0; i < NF; i++) den *= rs[i];
            out[0] = num / den;
            g_count = 0;   // deterministic graph replay
        }
    }
}

extern "C" void kernel_launch(void* const* d_in, const int* in_sizes, int n_in,
                              void* d_out, int out_size) {
    const float* X = (const float*)d_in[0];
    const float* a = (const float*)d_in[1];
    const float* b = (const float*)d_in[2];
    const float* y = (const float*)d_in[3];
    float* out = (float*)d_out;

    int smem_bytes = NSTAGE * SEGB;   // 93312 B
    cudaFuncSetAttribute(sum_kernel,
                         cudaFuncAttributeMaxDynamicSharedMemorySize, smem_bytes);
    sum_kernel<<<GRID, TPB, smem_bytes>>>(X, a, b, (const float4*)y, out);
}